// round 1
// baseline (speedup 1.0000x reference)
#include <cuda_runtime.h>
#include <cuda_bf16.h>
#include <math.h>

#define BATCH 2
#define NPTS  8192
#define CH    128
#define KNN   8
#define MTOT  (BATCH * NPTS)

// ---------------- scratch (no allocations allowed) ----------------
__device__ float g_q[MTOT * CH];
__device__ float g_k[MTOT * CH];
__device__ float g_v[MTOT * CH];
__device__ float g_agg[MTOT * CH];
__device__ int   g_idx[MTOT * KNN];

// ---------------- shared 128x128-tile GEMM:  Y = X @ W^T ----------------
// X: (M,128) row-major, W: (128,128) row-major (out,in), Y: (M,128)
// CTA = 128 rows of X, all 128 output cols. K=128 in 4 chunks of 32.
__device__ __forceinline__ void gemm_tile(const float* __restrict__ X,
                                          const float* __restrict__ W,
                                          float* __restrict__ Y, int m0)
{
    __shared__ float As[32][132];   // [k][m]
    __shared__ float Bs[32][132];   // [k][n] = W[n][k]
    const int tid = threadIdx.x;
    const int tx = tid & 15;        // output col group
    const int ty = tid >> 4;        // output row group
    float acc[8][8];
#pragma unroll
    for (int i = 0; i < 8; i++)
#pragma unroll
        for (int j = 0; j < 8; j++) acc[i][j] = 0.f;

    for (int kc = 0; kc < CH; kc += 32) {
#pragma unroll
        for (int i = 0; i < 4; i++) {
            int s  = tid + i * 256;    // 0..1023 float4 slots
            int r  = s >> 3;           // 0..127
            int kk = (s & 7) * 4;      // 0,4,...,28
            float4 xv = *(const float4*)(X + (size_t)(m0 + r) * CH + kc + kk);
            As[kk + 0][r] = xv.x; As[kk + 1][r] = xv.y;
            As[kk + 2][r] = xv.z; As[kk + 3][r] = xv.w;
            float4 wv = *(const float4*)(W + (size_t)r * CH + kc + kk);
            Bs[kk + 0][r] = wv.x; Bs[kk + 1][r] = wv.y;
            Bs[kk + 2][r] = wv.z; Bs[kk + 3][r] = wv.w;
        }
        __syncthreads();
#pragma unroll
        for (int kk = 0; kk < 32; kk++) {
            float a[8], b[8];
#pragma unroll
            for (int i = 0; i < 8; i++) a[i] = As[kk][ty * 8 + i];
#pragma unroll
            for (int j = 0; j < 8; j++) b[j] = Bs[kk][tx * 8 + j];
#pragma unroll
            for (int i = 0; i < 8; i++)
#pragma unroll
                for (int j = 0; j < 8; j++)
                    acc[i][j] = fmaf(a[i], b[j], acc[i][j]);
        }
        __syncthreads();
    }
#pragma unroll
    for (int i = 0; i < 8; i++) {
#pragma unroll
        for (int j = 0; j < 8; j += 4) {
            float4 o = make_float4(acc[i][j], acc[i][j + 1], acc[i][j + 2], acc[i][j + 3]);
            *(float4*)(Y + (size_t)(m0 + ty * 8 + i) * CH + tx * 8 + j) = o;
        }
    }
}

__global__ __launch_bounds__(256) void qkv_kernel(const float* __restrict__ feats,
                                                  const float* __restrict__ Wq,
                                                  const float* __restrict__ Wk,
                                                  const float* __restrict__ Wv)
{
    int m0 = blockIdx.x * 128;
    if (blockIdx.y == 0)      gemm_tile(feats, Wq, g_q, m0);
    else if (blockIdx.y == 1) gemm_tile(feats, Wk, g_k, m0);
    else                      gemm_tile(feats, Wv, g_v, m0);
}

__global__ __launch_bounds__(256) void out_gemm_kernel(const float* __restrict__ Wo,
                                                       float* __restrict__ out)
{
    gemm_tile(g_agg, Wo, out, blockIdx.x * 128);
}

// ---------------- KNN: top-8 nearest (incl self) per query ----------------
// One warp per query, 16 queries/CTA (512 threads). Candidates staged in
// smem chunks of 2048 (SoA x/y/z/sq = 32 KB). Each lane scans an interleaved
// 1/32 slice keeping a sorted ascending top-8, then an 8-round warp merge.
#define QPC    16
#define CCHUNK 2048

__global__ __launch_bounds__(512) void knn_kernel(const float* __restrict__ coords,
                                                  int* __restrict__ out_idx)
{
    __shared__ float sx[CCHUNK], sy[CCHUNK], sz[CCHUNK], ssq[CCHUNK];
    const int b    = blockIdx.y;
    const int q    = blockIdx.x * QPC + (threadIdx.x >> 5);
    const int lane = threadIdx.x & 31;
    const float* cb = coords + (size_t)b * NPTS * 3;

    const float qx = cb[q * 3 + 0], qy = cb[q * 3 + 1], qz = cb[q * 3 + 2];
    const float qsq = fmaf(qz, qz, fmaf(qy, qy, qx * qx));

    float w[KNN]; int id[KNN];
#pragma unroll
    for (int i = 0; i < KNN; i++) { w[i] = 3.0e38f; id[i] = -1; }

    for (int c0 = 0; c0 < NPTS; c0 += CCHUNK) {
        __syncthreads();
        for (int t = threadIdx.x; t < CCHUNK; t += 512) {
            float x = cb[(c0 + t) * 3 + 0];
            float y = cb[(c0 + t) * 3 + 1];
            float z = cb[(c0 + t) * 3 + 2];
            sx[t] = x; sy[t] = y; sz[t] = z;
            ssq[t] = fmaf(z, z, fmaf(y, y, x * x));
        }
        __syncthreads();
#pragma unroll 4
        for (int t = lane; t < CCHUNK; t += 32) {
            float dot = qx * sx[t];
            dot = fmaf(qy, sy[t], dot);
            dot = fmaf(qz, sz[t], dot);
            float d2 = fmaf(-2.f, dot, qsq + ssq[t]);   // same form as reference
            if (d2 < w[KNN - 1]) {
                w[KNN - 1]  = d2;
                id[KNN - 1] = c0 + t;
#pragma unroll
                for (int s = KNN - 1; s > 0; --s) {
                    if (w[s] < w[s - 1]) {
                        float tw = w[s]; w[s] = w[s - 1]; w[s - 1] = tw;
                        int   ti = id[s]; id[s] = id[s - 1]; id[s - 1] = ti;
                    }
                }
            }
        }
    }

    // warp merge: 8 rounds of pop-min across the 32 sorted lists
    const unsigned full = 0xffffffffu;
    for (int r = 0; r < KNN; ++r) {
        float vm = w[0];
#pragma unroll
        for (int off = 16; off; off >>= 1)
            vm = fminf(vm, __shfl_xor_sync(full, vm, off));
        unsigned ball = __ballot_sync(full, w[0] == vm);
        int src  = __ffs(ball) - 1;
        int widx = __shfl_sync(full, id[0], src);
        if (lane == 0)
            out_idx[((size_t)b * NPTS + q) * KNN + r] = widx;
        if (lane == src) {
#pragma unroll
            for (int s = 0; s < KNN - 1; s++) { w[s] = w[s + 1]; id[s] = id[s + 1]; }
            w[KNN - 1] = 3.0e38f;
        }
    }
}

// ---------------- attention over K=8 neighbors ----------------
// One warp per query (lane owns 4 channels). Gathers k/v rows (L2-resident).
__global__ __launch_bounds__(256) void attn_kernel(const float* __restrict__ coords,
                                                   const float* __restrict__ logg)
{
    const int gq   = blockIdx.x * 8 + (threadIdx.x >> 5);
    const int b    = gq >> 13;            // / 8192
    const int q    = gq & (NPTS - 1);
    const int lane = threadIdx.x & 31;
    const float lg = *logg;
    const float inv_sqrt_c = 0.08838834764831845f;   // 1/sqrt(128)

    const float* qrow = g_q + (size_t)gq * CH;
    float qv[4];
#pragma unroll
    for (int p = 0; p < 4; p++) qv[p] = qrow[lane + 32 * p];

    const float* cb = coords + (size_t)b * NPTS * 3;
    const float qx = cb[q * 3 + 0], qy = cb[q * 3 + 1], qz = cb[q * 3 + 2];

    int nb[KNN];
#pragma unroll
    for (int t = 0; t < KNN; t++) nb[t] = g_idx[(size_t)gq * KNN + t];

    float sc[KNN];
#pragma unroll
    for (int t = 0; t < KNN; t++) {
        const float* kr = g_k + ((size_t)b * NPTS + nb[t]) * CH;
        float d = 0.f;
#pragma unroll
        for (int p = 0; p < 4; p++) d = fmaf(qv[p], kr[lane + 32 * p], d);
#pragma unroll
        for (int off = 16; off; off >>= 1) d += __shfl_xor_sync(0xffffffffu, d, off);
        float dx = qx - cb[nb[t] * 3 + 0];
        float dy = qy - cb[nb[t] * 3 + 1];
        float dz = qz - cb[nb[t] * 3 + 2];
        float d2 = fmaf(dz, dz, fmaf(dy, dy, dx * dx));
        float dist = (d2 > 0.f) ? sqrtf(d2) : 0.f;     // _safe_norm
        float gw = expf(lg * dist);
        sc[t] = d * inv_sqrt_c * gw;
    }
    // softmax over K
    float m = sc[0];
#pragma unroll
    for (int t = 1; t < KNN; t++) m = fmaxf(m, sc[t]);
    float ssum = 0.f;
#pragma unroll
    for (int t = 0; t < KNN; t++) { sc[t] = expf(sc[t] - m); ssum += sc[t]; }
    float inv = 1.f / ssum;

    float acc[4] = {0.f, 0.f, 0.f, 0.f};
#pragma unroll
    for (int t = 0; t < KNN; t++) {
        const float* vr = g_v + ((size_t)b * NPTS + nb[t]) * CH;
        float wt = sc[t] * inv;
#pragma unroll
        for (int p = 0; p < 4; p++) acc[p] = fmaf(wt, vr[lane + 32 * p], acc[p]);
    }
#pragma unroll
    for (int p = 0; p < 4; p++) g_agg[(size_t)gq * CH + lane + 32 * p] = acc[p];
}

// ---------------- launch ----------------
extern "C" void kernel_launch(void* const* d_in, const int* in_sizes, int n_in,
                              void* d_out, int out_size)
{
    const float* feats  = (const float*)d_in[0];
    const float* coords = (const float*)d_in[1];
    const float* Wq     = (const float*)d_in[2];
    const float* Wk     = (const float*)d_in[3];
    const float* Wv     = (const float*)d_in[4];
    const float* Wo     = (const float*)d_in[5];
    const float* logg   = (const float*)d_in[6];
    float* out = (float*)d_out;

    int* idx_ptr = nullptr;
    cudaGetSymbolAddress((void**)&idx_ptr, g_idx);

    // q,k,v projections: 128 M-tiles x 3 weights
    qkv_kernel<<<dim3(MTOT / 128, 3), 256>>>(feats, Wq, Wk, Wv);

    // KNN top-8 per query
    knn_kernel<<<dim3(NPTS / QPC, BATCH), 512>>>(coords, idx_ptr);

    // neighbor attention -> g_agg
    attn_kernel<<<MTOT / 8, 256>>>(coords, logg);

    // output projection
    out_gemm_kernel<<<MTOT / 128, 256>>>(Wo, out);
}

// round 2
// speedup vs baseline: 1.6977x; 1.6977x over previous
#include <cuda_runtime.h>
#include <cuda_bf16.h>
#include <math.h>

#define BATCH 2
#define NPTS  8192
#define CH    128
#define KNN   8
#define MTOT  (BATCH * NPTS)

// ---------------- scratch (no allocations allowed) ----------------
__device__ float g_q[MTOT * CH];
__device__ float g_k[MTOT * CH];
__device__ float g_v[MTOT * CH];
__device__ float g_agg[MTOT * CH];
__device__ int   g_idx[MTOT * KNN];

// ---------------- f32x2 helpers (Blackwell packed fp32 FMA) ----------------
typedef unsigned long long ull;
__device__ __forceinline__ void fma2(ull& d, ull a, ull b) {
    asm("fma.rn.f32x2 %0, %1, %2, %0;" : "+l"(d) : "l"(a), "l"(b));
}
__device__ __forceinline__ ull pk2(float x, float y) {
    ull r; asm("mov.b64 %0, {%1, %2};" : "=l"(r) : "f"(x), "f"(y)); return r;
}
__device__ __forceinline__ float2 unpk2(ull v) {
    float2 f; asm("mov.b64 {%0, %1}, %2;" : "=f"(f.x), "=f"(f.y) : "l"(v)); return f;
}

// ---------------- 64x128 tile GEMM:  Y = X @ W^T  (f32x2 inner) ----------------
// X: (M,128) row-major, W: (128,128) row-major (out,in), Y: (M,128)
// CTA = 64 rows, 256 threads (16x16). Thread: 4 rows x 8 cols (4 f32x2 pairs).
__device__ __forceinline__ void gemm_tile64(const float* __restrict__ X,
                                            const float* __restrict__ W,
                                            float* __restrict__ Y, int m0)
{
    __shared__ float As[32][68];    // [k][m] 64 rows (+pad, 272B row = 16B aligned)
    __shared__ float Bs[32][132];   // [k][n] = W[n][k]
    const int tid = threadIdx.x;
    const int tx  = tid & 15;       // col groups: pairs at 2*tx + 32*j
    const int ty  = tid >> 4;       // rows ty*4 .. ty*4+3

    ull acc[4][4];
#pragma unroll
    for (int i = 0; i < 4; i++)
#pragma unroll
        for (int j = 0; j < 4; j++) acc[i][j] = 0ULL;

    for (int kc = 0; kc < CH; kc += 32) {
        // stage X tile: 64x32 = 512 float4 slots, 2 per thread
#pragma unroll
        for (int i = 0; i < 2; i++) {
            int s  = tid + i * 256;
            int r  = s >> 3;
            int kk = (s & 7) * 4;
            float4 xv = *(const float4*)(X + (size_t)(m0 + r) * CH + kc + kk);
            As[kk + 0][r] = xv.x; As[kk + 1][r] = xv.y;
            As[kk + 2][r] = xv.z; As[kk + 3][r] = xv.w;
        }
        // stage W tile: 128x32 = 1024 float4 slots, 4 per thread
#pragma unroll
        for (int i = 0; i < 4; i++) {
            int s  = tid + i * 256;
            int r  = s >> 3;
            int kk = (s & 7) * 4;
            float4 wv = *(const float4*)(W + (size_t)r * CH + kc + kk);
            Bs[kk + 0][r] = wv.x; Bs[kk + 1][r] = wv.y;
            Bs[kk + 2][r] = wv.z; Bs[kk + 3][r] = wv.w;
        }
        __syncthreads();
#pragma unroll
        for (int kk = 0; kk < 32; kk++) {
            float4 a4 = *(const float4*)&As[kk][ty * 4];
            ull a2[4] = { pk2(a4.x, a4.x), pk2(a4.y, a4.y),
                          pk2(a4.z, a4.z), pk2(a4.w, a4.w) };
            ull b2[4];
#pragma unroll
            for (int j = 0; j < 4; j++) {
                float2 bb = *(const float2*)&Bs[kk][tx * 2 + 32 * j];
                b2[j] = pk2(bb.x, bb.y);
            }
#pragma unroll
            for (int i = 0; i < 4; i++)
#pragma unroll
                for (int j = 0; j < 4; j++)
                    fma2(acc[i][j], a2[i], b2[j]);
        }
        __syncthreads();
    }
#pragma unroll
    for (int i = 0; i < 4; i++)
#pragma unroll
        for (int j = 0; j < 4; j++) {
            float2 o = unpk2(acc[i][j]);
            *(float2*)(Y + (size_t)(m0 + ty * 4 + i) * CH + tx * 2 + 32 * j) = o;
        }
}

__global__ __launch_bounds__(256) void qkv_kernel(const float* __restrict__ feats,
                                                  const float* __restrict__ Wq,
                                                  const float* __restrict__ Wk,
                                                  const float* __restrict__ Wv)
{
    int m0 = blockIdx.x * 64;
    if (blockIdx.y == 0)      gemm_tile64(feats, Wq, g_q, m0);
    else if (blockIdx.y == 1) gemm_tile64(feats, Wk, g_k, m0);
    else                      gemm_tile64(feats, Wv, g_v, m0);
}

__global__ __launch_bounds__(256) void out_gemm_kernel(const float* __restrict__ Wo,
                                                       float* __restrict__ out)
{
    gemm_tile64(g_agg, Wo, out, blockIdx.x * 64);
}

// ---------------- KNN: warp-collective top-8, 4 queries per warp ----------------
// Lane j<8 holds the j-th smallest (d2,idx) of the warp-shared sorted list.
// thr = current 8th best (warp-uniform). Inserts happen ~55x per query total,
// handled branch-uniformly via ballot. Candidates staged as float4 in smem.
#define QW     4
#define WARPS  8
#define CCH    2048

__global__ __launch_bounds__(256) void knn_kernel(const float* __restrict__ coords,
                                                  int* __restrict__ out_idx)
{
    __shared__ float4 sc[CCH];
    const unsigned full = 0xffffffffu;
    const int b     = blockIdx.y;
    const int warp  = threadIdx.x >> 5;
    const int lane  = threadIdx.x & 31;
    const int qbase = blockIdx.x * (WARPS * QW) + warp * QW;
    const float* cb = coords + (size_t)b * NPTS * 3;

    float qx[QW], qy[QW], qz[QW], qs[QW];
#pragma unroll
    for (int u = 0; u < QW; u++) {
        qx[u] = cb[(qbase + u) * 3 + 0];
        qy[u] = cb[(qbase + u) * 3 + 1];
        qz[u] = cb[(qbase + u) * 3 + 2];
        qs[u] = fmaf(qz[u], qz[u], fmaf(qy[u], qy[u], qx[u] * qx[u]));
    }

    float val[QW]; int idx[QW]; float thr[QW];
#pragma unroll
    for (int u = 0; u < QW; u++) { val[u] = 3.0e38f; idx[u] = -1; thr[u] = 3.0e38f; }

    for (int c0 = 0; c0 < NPTS; c0 += CCH) {
        __syncthreads();
        for (int t = threadIdx.x; t < CCH; t += 256) {
            float x = cb[(c0 + t) * 3 + 0];
            float y = cb[(c0 + t) * 3 + 1];
            float z = cb[(c0 + t) * 3 + 2];
            sc[t] = make_float4(x, y, z, fmaf(z, z, fmaf(y, y, x * x)));
        }
        __syncthreads();

        for (int t = lane; t < CCH; t += 32) {
            float4 c = sc[t];
            int cbase = c0 + t - lane;   // t - lane is warp-uniform
#pragma unroll
            for (int u = 0; u < QW; u++) {
                float dot = qx[u] * c.x;
                dot = fmaf(qy[u], c.y, dot);
                dot = fmaf(qz[u], c.z, dot);
                float d2 = fmaf(-2.f, dot, qs[u] + c.w);   // same form as reference
                unsigned m = __ballot_sync(full, d2 < thr[u]);
                while (m) {
                    int src = __ffs(m) - 1;
                    m &= m - 1;
                    float dn = __shfl_sync(full, d2, src);
                    if (dn < thr[u]) {                     // warp-uniform branch
                        int in = cbase + src;
                        float pv = __shfl_up_sync(full, val[u], 1);
                        int   pi = __shfl_up_sync(full, idx[u], 1);
                        unsigned le = __ballot_sync(full, val[u] <= dn);
                        int pos = __popc(le & 0xff);       // stable: ties go after
                        if (lane == pos)               { val[u] = dn; idx[u] = in; }
                        else if (lane > pos && lane < 8) { val[u] = pv; idx[u] = pi; }
                        thr[u] = __shfl_sync(full, val[u], 7);
                    }
                }
            }
        }
    }

    if (lane < KNN) {
#pragma unroll
        for (int u = 0; u < QW; u++)
            out_idx[((size_t)b * NPTS + qbase + u) * KNN + lane] = idx[u];
    }
}

// ---------------- attention over K=8 neighbors ----------------
__global__ __launch_bounds__(256) void attn_kernel(const float* __restrict__ coords,
                                                   const float* __restrict__ logg)
{
    const int gq   = blockIdx.x * 8 + (threadIdx.x >> 5);
    const int b    = gq >> 13;
    const int q    = gq & (NPTS - 1);
    const int lane = threadIdx.x & 31;
    const float lg = *logg;
    const float inv_sqrt_c = 0.08838834764831845f;   // 1/sqrt(128)

    const float* qrow = g_q + (size_t)gq * CH;
    float qv[4];
#pragma unroll
    for (int p = 0; p < 4; p++) qv[p] = qrow[lane + 32 * p];

    const float* cb = coords + (size_t)b * NPTS * 3;
    const float qx = cb[q * 3 + 0], qy = cb[q * 3 + 1], qz = cb[q * 3 + 2];

    int nb[KNN];
#pragma unroll
    for (int t = 0; t < KNN; t++) nb[t] = g_idx[(size_t)gq * KNN + t];

    float sc[KNN];
#pragma unroll
    for (int t = 0; t < KNN; t++) {
        const float* kr = g_k + ((size_t)b * NPTS + nb[t]) * CH;
        float d = 0.f;
#pragma unroll
        for (int p = 0; p < 4; p++) d = fmaf(qv[p], kr[lane + 32 * p], d);
#pragma unroll
        for (int off = 16; off; off >>= 1) d += __shfl_xor_sync(0xffffffffu, d, off);
        float dx = qx - cb[nb[t] * 3 + 0];
        float dy = qy - cb[nb[t] * 3 + 1];
        float dz = qz - cb[nb[t] * 3 + 2];
        float d2 = fmaf(dz, dz, fmaf(dy, dy, dx * dx));
        float dist = (d2 > 0.f) ? sqrtf(d2) : 0.f;     // _safe_norm
        float gw = expf(lg * dist);
        sc[t] = d * inv_sqrt_c * gw;
    }
    float m = sc[0];
#pragma unroll
    for (int t = 1; t < KNN; t++) m = fmaxf(m, sc[t]);
    float ssum = 0.f;
#pragma unroll
    for (int t = 0; t < KNN; t++) { sc[t] = expf(sc[t] - m); ssum += sc[t]; }
    float inv = 1.f / ssum;

    float acc[4] = {0.f, 0.f, 0.f, 0.f};
#pragma unroll
    for (int t = 0; t < KNN; t++) {
        const float* vr = g_v + ((size_t)b * NPTS + nb[t]) * CH;
        float wt = sc[t] * inv;
#pragma unroll
        for (int p = 0; p < 4; p++) acc[p] = fmaf(wt, vr[lane + 32 * p], acc[p]);
    }
#pragma unroll
    for (int p = 0; p < 4; p++) g_agg[(size_t)gq * CH + lane + 32 * p] = acc[p];
}

// ---------------- launch ----------------
extern "C" void kernel_launch(void* const* d_in, const int* in_sizes, int n_in,
                              void* d_out, int out_size)
{
    const float* feats  = (const float*)d_in[0];
    const float* coords = (const float*)d_in[1];
    const float* Wq     = (const float*)d_in[2];
    const float* Wk     = (const float*)d_in[3];
    const float* Wv     = (const float*)d_in[4];
    const float* Wo     = (const float*)d_in[5];
    const float* logg   = (const float*)d_in[6];
    float* out = (float*)d_out;

    int* idx_ptr = nullptr;
    cudaGetSymbolAddress((void**)&idx_ptr, g_idx);

    // q,k,v projections: 256 M-tiles x 3 weights = 768 CTAs
    qkv_kernel<<<dim3(MTOT / 64, 3), 256>>>(feats, Wq, Wk, Wv);

    // KNN top-8 per query: 32 queries/CTA
    knn_kernel<<<dim3(NPTS / (WARPS * QW), BATCH), 256>>>(coords, idx_ptr);

    // neighbor attention -> g_agg
    attn_kernel<<<MTOT / 8, 256>>>(coords, logg);

    // output projection: 256 CTAs
    out_gemm_kernel<<<MTOT / 64, 256>>>(Wo, out);
}

// round 3
// speedup vs baseline: 1.9047x; 1.1219x over previous
#include <cuda_runtime.h>
#include <cuda_bf16.h>
#include <math.h>

#define BATCH 2
#define NPTS  8192
#define CH    128
#define KNN   8
#define MTOT  (BATCH * NPTS)

// ---------------- scratch (no allocations allowed) ----------------
__device__ float g_q[MTOT * CH];
__device__ float g_k[MTOT * CH];
__device__ float g_v[MTOT * CH];
__device__ int   g_idx[MTOT * KNN];
// hi/lo bf16-split operands: per fp32 scalar -> 4 bf16 (K' = 512)
__device__ uint4 g_x2[MTOT * 64];      // feats split, X-pattern (hi,lo,hi,lo)
__device__ uint4 g_agg2[MTOT * 64];    // agg split,   X-pattern
__device__ uint4 g_w2[4 * 8192];       // Wq,Wk,Wv,Wo split, W-pattern (hi,hi,lo,lo)

// ---------------- fp32 -> (hi,lo) bf16 split helpers ----------------
__device__ __forceinline__ void split_bf16(float x, unsigned short& h, unsigned short& l) {
    __nv_bfloat16 hb = __float2bfloat16(x);
    float hf = __bfloat162float(hb);
    __nv_bfloat16 lb = __float2bfloat16(x - hf);
    h = __bfloat16_as_ushort(hb);
    l = __bfloat16_as_ushort(lb);
}

// X-pattern packed word: (hi, lo) as bf16x2 (hi at low half / lower address)
__device__ __forceinline__ unsigned pack_hilo(float x) {
    unsigned short h, l; split_bf16(x, h, l);
    return ((unsigned)l << 16) | (unsigned)h;
}

__global__ __launch_bounds__(256) void conv_feats_kernel(const float* __restrict__ feats)
{
    int idx = blockIdx.x * 256 + threadIdx.x;          // m*128 + k
    unsigned p = pack_hilo(feats[idx]);
    ((uint2*)g_x2)[idx] = make_uint2(p, p);            // (hi,lo,hi,lo)
}

__global__ __launch_bounds__(256) void conv_w_kernel(const float* __restrict__ Wq,
                                                     const float* __restrict__ Wk,
                                                     const float* __restrict__ Wv,
                                                     const float* __restrict__ Wo)
{
    int idx = blockIdx.x * 256 + threadIdx.x;          // w*16384 + n*128 + k
    int w = idx >> 14, e = idx & 16383;
    const float* W = (w == 0) ? Wq : (w == 1) ? Wk : (w == 2) ? Wv : Wo;
    unsigned short h, l; split_bf16(W[e], h, l);
    unsigned p0 = ((unsigned)h << 16) | h;             // (hi,hi)
    unsigned p1 = ((unsigned)l << 16) | l;             // (lo,lo)
    ((uint2*)g_w2)[idx] = make_uint2(p0, p1);          // (hi,hi,lo,lo)
}

// ---------------- tensor-core GEMM:  Y = X @ W^T via bf16 split-K ----------------
// X2: (M,512) bf16 row-major (as uint4, 64 per row), W2: (128,512) bf16.
// CTA = 128 rows x 128 cols, 256 threads = 8 warps (4x2), warp tile 32x64.
// mma.m16n8k16 row.col; all fragment regs are k-adjacent pairs -> plain LDS.32.
// smem rows padded to 144B -> fragment loads are bank-conflict-free.
__device__ __forceinline__ void mma_gemm_tile(const uint4* __restrict__ X2,
                                              const uint4* __restrict__ W2,
                                              float* __restrict__ Y, int m0)
{
    __shared__ __align__(16) unsigned char xs[128 * 144];
    __shared__ __align__(16) unsigned char ws[128 * 144];
    const int tid  = threadIdx.x;
    const int lane = tid & 31;
    const int warp = tid >> 5;
    const int wm   = warp >> 1;       // 0..3 -> rows wm*32
    const int wn   = warp & 1;        // 0..1 -> cols wn*64
    const int g    = lane >> 2;       // group id 0..7
    const int c4   = lane & 3;

    float acc[2][8][4];
#pragma unroll
    for (int i = 0; i < 2; i++)
#pragma unroll
        for (int t = 0; t < 8; t++)
#pragma unroll
            for (int r = 0; r < 4; r++) acc[i][t][r] = 0.f;

    for (int kc = 0; kc < 8; kc++) {        // K' = 512 in chunks of 64
        __syncthreads();
#pragma unroll
        for (int i = 0; i < 4; i++) {
            int s  = tid + i * 256;         // 0..1023
            int r  = s >> 3;                // row 0..127
            int f4 = s & 7;                 // 16B unit 0..7
            *(uint4*)(xs + r * 144 + f4 * 16) = X2[(size_t)(m0 + r) * 64 + kc * 8 + f4];
            *(uint4*)(ws + r * 144 + f4 * 16) = W2[(size_t)r * 64 + kc * 8 + f4];
        }
        __syncthreads();
#pragma unroll
        for (int ks = 0; ks < 4; ks++) {    // 4 x k16 steps
            unsigned a[2][4], b[8][2];
#pragma unroll
            for (int i = 0; i < 2; i++)
#pragma unroll
                for (int j = 0; j < 4; j++) {
                    int row = wm * 32 + i * 16 + g + 8 * (j & 1);
                    int off = ks * 32 + (j >> 1) * 16 + c4 * 4;
                    a[i][j] = *(const unsigned*)(xs + row * 144 + off);
                }
#pragma unroll
            for (int t = 0; t < 8; t++)
#pragma unroll
                for (int r = 0; r < 2; r++) {
                    int n   = wn * 64 + t * 8 + g;
                    int off = ks * 32 + r * 16 + c4 * 4;
                    b[t][r] = *(const unsigned*)(ws + n * 144 + off);
                }
#pragma unroll
            for (int i = 0; i < 2; i++)
#pragma unroll
                for (int t = 0; t < 8; t++)
                    asm volatile(
                        "mma.sync.aligned.m16n8k16.row.col.f32.bf16.bf16.f32 "
                        "{%0,%1,%2,%3}, {%4,%5,%6,%7}, {%8,%9}, {%0,%1,%2,%3};"
                        : "+f"(acc[i][t][0]), "+f"(acc[i][t][1]),
                          "+f"(acc[i][t][2]), "+f"(acc[i][t][3])
                        : "r"(a[i][0]), "r"(a[i][1]), "r"(a[i][2]), "r"(a[i][3]),
                          "r"(b[t][0]), "r"(b[t][1]));
        }
    }
#pragma unroll
    for (int i = 0; i < 2; i++)
#pragma unroll
        for (int t = 0; t < 8; t++) {
            int row = m0 + wm * 32 + i * 16 + g;
            int col = wn * 64 + t * 8 + 2 * c4;
            *(float2*)(Y + (size_t)row * CH + col)       = make_float2(acc[i][t][0], acc[i][t][1]);
            *(float2*)(Y + (size_t)(row + 8) * CH + col) = make_float2(acc[i][t][2], acc[i][t][3]);
        }
}

__global__ __launch_bounds__(256) void qkv_mma_kernel()
{
    const uint4* W2 = g_w2 + (size_t)blockIdx.y * 8192;
    float* Y = (blockIdx.y == 0) ? g_q : (blockIdx.y == 1) ? g_k : g_v;
    mma_gemm_tile(g_x2, W2, Y, blockIdx.x * 128);
}

__global__ __launch_bounds__(256) void out_mma_kernel(float* __restrict__ out)
{
    mma_gemm_tile(g_agg2, g_w2 + 3 * 8192, out, blockIdx.x * 128);
}

// ---------------- KNN: warp-collective top-8, 4 queries/warp, 4-cand vote batch ----
#define QW     4
#define WARPS  8
#define CCH    2048

__device__ __forceinline__ void try_insert(float d2, int base,
                                           float& val, int& idx, float& thr)
{
    const unsigned full = 0xffffffffu;
    unsigned m = __ballot_sync(full, d2 < thr);
    const int lane = threadIdx.x & 31;
    while (m) {
        int src = __ffs(m) - 1;
        m &= m - 1;
        float dn = __shfl_sync(full, d2, src);
        if (dn < thr) {                         // warp-uniform
            int   in = base + src;
            float pv = __shfl_up_sync(full, val, 1);
            int   pi = __shfl_up_sync(full, idx, 1);
            unsigned le = __ballot_sync(full, val <= dn);
            int pos = __popc(le & 0xff);
            if (lane == pos)                  { val = dn; idx = in; }
            else if (lane > pos && lane < 8)  { val = pv; idx = pi; }
            thr = __shfl_sync(full, val, 7);
        }
    }
}

__global__ __launch_bounds__(256) void knn_kernel(const float* __restrict__ coords,
                                                  int* __restrict__ out_idx)
{
    __shared__ float4 sc[CCH];
    const unsigned full = 0xffffffffu;
    const int b     = blockIdx.y;
    const int warp  = threadIdx.x >> 5;
    const int lane  = threadIdx.x & 31;
    const int qbase = blockIdx.x * (WARPS * QW) + warp * QW;
    const float* cb = coords + (size_t)b * NPTS * 3;

    float qx[QW], qy[QW], qz[QW], qs[QW];
#pragma unroll
    for (int u = 0; u < QW; u++) {
        qx[u] = cb[(qbase + u) * 3 + 0];
        qy[u] = cb[(qbase + u) * 3 + 1];
        qz[u] = cb[(qbase + u) * 3 + 2];
        qs[u] = fmaf(qz[u], qz[u], fmaf(qy[u], qy[u], qx[u] * qx[u]));
    }

    float val[QW]; int idx[QW]; float thr[QW];
#pragma unroll
    for (int u = 0; u < QW; u++) { val[u] = 3.0e38f; idx[u] = -1; thr[u] = 3.0e38f; }

    for (int c0 = 0; c0 < NPTS; c0 += CCH) {
        __syncthreads();
        for (int t = threadIdx.x; t < CCH; t += 256) {
            float x = cb[(c0 + t) * 3 + 0];
            float y = cb[(c0 + t) * 3 + 1];
            float z = cb[(c0 + t) * 3 + 2];
            sc[t] = make_float4(x, y, z, fmaf(z, z, fmaf(y, y, x * x)));
        }
        __syncthreads();

        for (int t = lane; t < CCH; t += 128) {       // 4 candidates per lane
            float4 ca = sc[t];
            float4 cbv = sc[t + 32];
            float4 cc = sc[t + 64];
            float4 cd = sc[t + 96];
            int tb = c0 + t - lane;                   // warp-uniform
#pragma unroll
            for (int u = 0; u < QW; u++) {
                float da = fmaf(-2.f, fmaf(qz[u], ca.z,  fmaf(qy[u], ca.y,  qx[u] * ca.x)),  qs[u] + ca.w);
                float db = fmaf(-2.f, fmaf(qz[u], cbv.z, fmaf(qy[u], cbv.y, qx[u] * cbv.x)), qs[u] + cbv.w);
                float dc = fmaf(-2.f, fmaf(qz[u], cc.z,  fmaf(qy[u], cc.y,  qx[u] * cc.x)),  qs[u] + cc.w);
                float dd = fmaf(-2.f, fmaf(qz[u], cd.z,  fmaf(qy[u], cd.y,  qx[u] * cd.x)),  qs[u] + cd.w);
                float mn = fminf(fminf(da, db), fminf(dc, dd));
                if (__any_sync(full, mn < thr[u])) {
                    try_insert(da, tb,      val[u], idx[u], thr[u]);
                    try_insert(db, tb + 32, val[u], idx[u], thr[u]);
                    try_insert(dc, tb + 64, val[u], idx[u], thr[u]);
                    try_insert(dd, tb + 96, val[u], idx[u], thr[u]);
                }
            }
        }
    }

    if (lane < KNN) {
#pragma unroll
        for (int u = 0; u < QW; u++)
            out_idx[((size_t)b * NPTS + qbase + u) * KNN + lane] = idx[u];
    }
}

// ---------------- attention over K=8 neighbors (writes bf16 hi/lo agg) ----------
__global__ __launch_bounds__(256) void attn_kernel(const float* __restrict__ coords,
                                                   const float* __restrict__ logg)
{
    const int gq   = blockIdx.x * 8 + (threadIdx.x >> 5);
    const int b    = gq >> 13;
    const int q    = gq & (NPTS - 1);
    const int lane = threadIdx.x & 31;
    const float lg = *logg;
    const float inv_sqrt_c = 0.08838834764831845f;   // 1/sqrt(128)

    const float* qrow = g_q + (size_t)gq * CH;
    float qv[4];
#pragma unroll
    for (int p = 0; p < 4; p++) qv[p] = qrow[lane + 32 * p];

    const float* cb = coords + (size_t)b * NPTS * 3;
    const float qx = cb[q * 3 + 0], qy = cb[q * 3 + 1], qz = cb[q * 3 + 2];

    int nb[KNN];
#pragma unroll
    for (int t = 0; t < KNN; t++) nb[t] = g_idx[(size_t)gq * KNN + t];

    float sc[KNN];
#pragma unroll
    for (int t = 0; t < KNN; t++) {
        const float* kr = g_k + ((size_t)b * NPTS + nb[t]) * CH;
        float d = 0.f;
#pragma unroll
        for (int p = 0; p < 4; p++) d = fmaf(qv[p], kr[lane + 32 * p], d);
#pragma unroll
        for (int off = 16; off; off >>= 1) d += __shfl_xor_sync(0xffffffffu, d, off);
        float dx = qx - cb[nb[t] * 3 + 0];
        float dy = qy - cb[nb[t] * 3 + 1];
        float dz = qz - cb[nb[t] * 3 + 2];
        float d2 = fmaf(dz, dz, fmaf(dy, dy, dx * dx));
        float dist = (d2 > 0.f) ? sqrtf(d2) : 0.f;     // _safe_norm
        float gw = expf(lg * dist);
        sc[t] = d * inv_sqrt_c * gw;
    }
    float m = sc[0];
#pragma unroll
    for (int t = 1; t < KNN; t++) m = fmaxf(m, sc[t]);
    float ssum = 0.f;
#pragma unroll
    for (int t = 0; t < KNN; t++) { sc[t] = expf(sc[t] - m); ssum += sc[t]; }
    float inv = 1.f / ssum;

    float acc[4] = {0.f, 0.f, 0.f, 0.f};
#pragma unroll
    for (int t = 0; t < KNN; t++) {
        const float* vr = g_v + ((size_t)b * NPTS + nb[t]) * CH;
        float wt = sc[t] * inv;
#pragma unroll
        for (int p = 0; p < 4; p++) acc[p] = fmaf(wt, vr[lane + 32 * p], acc[p]);
    }
    // write agg directly in bf16 hi/lo X-pattern for the output GEMM
#pragma unroll
    for (int p = 0; p < 4; p++) {
        unsigned pk = pack_hilo(acc[p]);
        ((uint2*)g_agg2)[(size_t)gq * 128 + lane + 32 * p] = make_uint2(pk, pk);
    }
}

// ---------------- launch ----------------
extern "C" void kernel_launch(void* const* d_in, const int* in_sizes, int n_in,
                              void* d_out, int out_size)
{
    const float* feats  = (const float*)d_in[0];
    const float* coords = (const float*)d_in[1];
    const float* Wq     = (const float*)d_in[2];
    const float* Wk     = (const float*)d_in[3];
    const float* Wv     = (const float*)d_in[4];
    const float* Wo     = (const float*)d_in[5];
    const float* logg   = (const float*)d_in[6];
    float* out = (float*)d_out;

    int* idx_ptr = nullptr;
    cudaGetSymbolAddress((void**)&idx_ptr, g_idx);

    // split fp32 operands into bf16 hi/lo
    conv_feats_kernel<<<MTOT * CH / 256, 256>>>(feats);
    conv_w_kernel<<<4 * CH * CH / 256, 256>>>(Wq, Wk, Wv, Wo);

    // q,k,v projections on tensor cores
    qkv_mma_kernel<<<dim3(MTOT / 128, 3), 256>>>();

    // KNN top-8 per query
    knn_kernel<<<dim3(NPTS / (WARPS * QW), BATCH), 256>>>(coords, idx_ptr);

    // neighbor attention -> g_agg2 (bf16 hi/lo)
    attn_kernel<<<MTOT / 8, 256>>>(coords, logg);

    // output projection on tensor cores
    out_mma_kernel<<<MTOT / 128, 256>>>(out);
}

// round 4
// speedup vs baseline: 1.9601x; 1.0291x over previous
#include <cuda_runtime.h>
#include <cuda_bf16.h>
#include <math.h>

#define BATCH 2
#define NPTS  8192
#define CH    128
#define KNN   8
#define MTOT  (BATCH * NPTS)

// ---------------- scratch (no allocations allowed) ----------------
__device__ float g_q[MTOT * CH];
__device__ float g_k[MTOT * CH];
__device__ float g_v[MTOT * CH];
__device__ int   g_idx[MTOT * KNN];
__device__ uint4 g_agg2[MTOT * 64];    // agg split, X-pattern (hi,lo,hi,lo)
__device__ uint4 g_w2[4 * 8192];       // Wq,Wk,Wv,Wo split, W-pattern (hi,hi,lo,lo)

// ---------------- f32x2 helpers (Blackwell packed fp32 math) ----------------
typedef unsigned long long ull;
__device__ __forceinline__ void fma2(ull& d, ull a, ull b) {
    asm("fma.rn.f32x2 %0, %1, %2, %0;" : "+l"(d) : "l"(a), "l"(b));
}
__device__ __forceinline__ ull mul2(ull a, ull b) {
    ull r; asm("mul.rn.f32x2 %0, %1, %2;" : "=l"(r) : "l"(a), "l"(b)); return r;
}
__device__ __forceinline__ ull pk2(float x, float y) {
    ull r; asm("mov.b64 %0, {%1, %2};" : "=l"(r) : "f"(x), "f"(y)); return r;
}
__device__ __forceinline__ float2 unpk2(ull v) {
    float2 f; asm("mov.b64 {%0, %1}, %2;" : "=f"(f.x), "=f"(f.y) : "l"(v)); return f;
}

// ---------------- fp32 -> (hi,lo) bf16 split helpers ----------------
__device__ __forceinline__ void split_bf16(float x, unsigned short& h, unsigned short& l) {
    __nv_bfloat16 hb = __float2bfloat16(x);
    float hf = __bfloat162float(hb);
    __nv_bfloat16 lb = __float2bfloat16(x - hf);
    h = __bfloat16_as_ushort(hb);
    l = __bfloat16_as_ushort(lb);
}
__device__ __forceinline__ unsigned pack_hilo(float x) {
    unsigned short h, l; split_bf16(x, h, l);
    return ((unsigned)l << 16) | (unsigned)h;
}

__global__ __launch_bounds__(256) void conv_w_kernel(const float* __restrict__ Wq,
                                                     const float* __restrict__ Wk,
                                                     const float* __restrict__ Wv,
                                                     const float* __restrict__ Wo)
{
    int idx = blockIdx.x * 256 + threadIdx.x;          // w*16384 + n*128 + k
    int w = idx >> 14, e = idx & 16383;
    const float* W = (w == 0) ? Wq : (w == 1) ? Wk : (w == 2) ? Wv : Wo;
    unsigned short h, l; split_bf16(W[e], h, l);
    unsigned p0 = ((unsigned)h << 16) | h;             // (hi,hi)
    unsigned p1 = ((unsigned)l << 16) | l;             // (lo,lo)
    ((uint2*)g_w2)[idx] = make_uint2(p0, p1);          // (hi,hi,lo,lo)
}

// ---------------- tensor-core GEMM:  Y = X @ W^T via bf16 split-K ----------------
// SPLIT_SRC=true: X is fp32 (M,128), converted hi/lo inline during staging.
// SPLIT_SRC=false: X is pre-split uint4 (M, 64) X-pattern.
// CTA = 128 rows x 128 cols, 256 threads = 8 warps (4x2), warp tile 32x64.
// mma.m16n8k16 row.col; smem rows padded to 144B -> conflict-free LDS.32 frags.
template <bool SPLIT_SRC>
__device__ __forceinline__ void mma_gemm_tile(const void* __restrict__ Xv,
                                              const uint4* __restrict__ W2,
                                              float* __restrict__ Y, int m0)
{
    __shared__ __align__(16) unsigned char xs[128 * 144];
    __shared__ __align__(16) unsigned char ws[128 * 144];
    const int tid  = threadIdx.x;
    const int lane = tid & 31;
    const int warp = tid >> 5;
    const int wm   = warp >> 1;
    const int wn   = warp & 1;
    const int g    = lane >> 2;
    const int c4   = lane & 3;

    float acc[2][8][4];
#pragma unroll
    for (int i = 0; i < 2; i++)
#pragma unroll
        for (int t = 0; t < 8; t++)
#pragma unroll
            for (int r = 0; r < 4; r++) acc[i][t][r] = 0.f;

    for (int kc = 0; kc < 8; kc++) {        // K' = 512 in chunks of 64
        __syncthreads();
#pragma unroll
        for (int i = 0; i < 4; i++) {
            int s  = tid + i * 256;         // 0..1023
            int r  = s >> 3;                // row 0..127
            int f4 = s & 7;                 // 16B unit 0..7
            if (SPLIT_SRC) {
                const float* X = (const float*)Xv;
                float2 xv = *(const float2*)(X + (size_t)(m0 + r) * CH + kc * 16 + f4 * 2);
                unsigned p0 = pack_hilo(xv.x), p1 = pack_hilo(xv.y);
                *(uint4*)(xs + r * 144 + f4 * 16) = make_uint4(p0, p0, p1, p1);
            } else {
                const uint4* X2 = (const uint4*)Xv;
                *(uint4*)(xs + r * 144 + f4 * 16) = X2[(size_t)(m0 + r) * 64 + kc * 8 + f4];
            }
            *(uint4*)(ws + r * 144 + f4 * 16) = W2[(size_t)r * 64 + kc * 8 + f4];
        }
        __syncthreads();
#pragma unroll
        for (int ks = 0; ks < 4; ks++) {    // 4 x k16 steps
            unsigned a[2][4], b[8][2];
#pragma unroll
            for (int i = 0; i < 2; i++)
#pragma unroll
                for (int j = 0; j < 4; j++) {
                    int row = wm * 32 + i * 16 + g + 8 * (j & 1);
                    int off = ks * 32 + (j >> 1) * 16 + c4 * 4;
                    a[i][j] = *(const unsigned*)(xs + row * 144 + off);
                }
#pragma unroll
            for (int t = 0; t < 8; t++)
#pragma unroll
                for (int r = 0; r < 2; r++) {
                    int n   = wn * 64 + t * 8 + g;
                    int off = ks * 32 + r * 16 + c4 * 4;
                    b[t][r] = *(const unsigned*)(ws + n * 144 + off);
                }
#pragma unroll
            for (int i = 0; i < 2; i++)
#pragma unroll
                for (int t = 0; t < 8; t++)
                    asm volatile(
                        "mma.sync.aligned.m16n8k16.row.col.f32.bf16.bf16.f32 "
                        "{%0,%1,%2,%3}, {%4,%5,%6,%7}, {%8,%9}, {%0,%1,%2,%3};"
                        : "+f"(acc[i][t][0]), "+f"(acc[i][t][1]),
                          "+f"(acc[i][t][2]), "+f"(acc[i][t][3])
                        : "r"(a[i][0]), "r"(a[i][1]), "r"(a[i][2]), "r"(a[i][3]),
                          "r"(b[t][0]), "r"(b[t][1]));
        }
    }
#pragma unroll
    for (int i = 0; i < 2; i++)
#pragma unroll
        for (int t = 0; t < 8; t++) {
            int row = m0 + wm * 32 + i * 16 + g;
            int col = wn * 64 + t * 8 + 2 * c4;
            *(float2*)(Y + (size_t)row * CH + col)       = make_float2(acc[i][t][0], acc[i][t][1]);
            *(float2*)(Y + (size_t)(row + 8) * CH + col) = make_float2(acc[i][t][2], acc[i][t][3]);
        }
}

__global__ __launch_bounds__(256) void qkv_mma_kernel(const float* __restrict__ feats)
{
    const uint4* W2 = g_w2 + (size_t)blockIdx.y * 8192;
    float* Y = (blockIdx.y == 0) ? g_q : (blockIdx.y == 1) ? g_k : g_v;
    mma_gemm_tile<true>(feats, W2, Y, blockIdx.x * 128);
}

__global__ __launch_bounds__(256) void out_mma_kernel(float* __restrict__ out)
{
    mma_gemm_tile<false>(g_agg2, g_w2 + 3 * 8192, out, blockIdx.x * 128);
}

// ---------------- KNN: warp-collective top-8 in e-space (e = csq - 2*dot) ------
// 4 queries/warp; distances via f32x2 packed FMA (2 candidates per instruction).
#define QW     4
#define WARPS  8
#define CCH    2048

__device__ __forceinline__ void try_insert(float d2, int base,
                                           float& val, int& idx, float& thr)
{
    const unsigned full = 0xffffffffu;
    unsigned m = __ballot_sync(full, d2 < thr);
    const int lane = threadIdx.x & 31;
    while (m) {
        int src = __ffs(m) - 1;
        m &= m - 1;
        float dn = __shfl_sync(full, d2, src);
        if (dn < thr) {                         // warp-uniform
            int   in = base + src;
            float pv = __shfl_up_sync(full, val, 1);
            int   pi = __shfl_up_sync(full, idx, 1);
            unsigned le = __ballot_sync(full, val <= dn);
            int pos = __popc(le & 0xff);
            if (lane == pos)                  { val = dn; idx = in; }
            else if (lane > pos && lane < 8)  { val = pv; idx = pi; }
            thr = __shfl_sync(full, val, 7);
        }
    }
}

__global__ __launch_bounds__(256) void knn_kernel(const float* __restrict__ coords,
                                                  int* __restrict__ out_idx)
{
    __shared__ float4 sc[CCH];
    const unsigned full = 0xffffffffu;
    const int b     = blockIdx.y;
    const int warp  = threadIdx.x >> 5;
    const int lane  = threadIdx.x & 31;
    const int qbase = blockIdx.x * (WARPS * QW) + warp * QW;
    const float* cb = coords + (size_t)b * NPTS * 3;

    ull qxp[QW], qyp[QW], qzp[QW];
#pragma unroll
    for (int u = 0; u < QW; u++) {
        float x = cb[(qbase + u) * 3 + 0];
        float y = cb[(qbase + u) * 3 + 1];
        float z = cb[(qbase + u) * 3 + 2];
        qxp[u] = pk2(x, x); qyp[u] = pk2(y, y); qzp[u] = pk2(z, z);
    }
    const ull n2p = pk2(-2.f, -2.f);

    float val[QW]; int idx[QW]; float thr[QW];
#pragma unroll
    for (int u = 0; u < QW; u++) { val[u] = 3.0e38f; idx[u] = -1; thr[u] = 3.0e38f; }

    for (int c0 = 0; c0 < NPTS; c0 += CCH) {
        __syncthreads();
        for (int t = threadIdx.x; t < CCH; t += 256) {
            float x = cb[(c0 + t) * 3 + 0];
            float y = cb[(c0 + t) * 3 + 1];
            float z = cb[(c0 + t) * 3 + 2];
            sc[t] = make_float4(x, y, z, fmaf(z, z, fmaf(y, y, x * x)));
        }
        __syncthreads();

        for (int t = lane; t < CCH; t += 128) {       // 4 candidates per lane
            float4 ca = sc[t];
            float4 cbv = sc[t + 32];
            float4 cc = sc[t + 64];
            float4 cd = sc[t + 96];
            // pack pairwise: (cand t, cand t+32) and (cand t+64, cand t+96)
            ull X01 = pk2(ca.x, cbv.x), Y01 = pk2(ca.y, cbv.y);
            ull Z01 = pk2(ca.z, cbv.z), S01 = pk2(ca.w, cbv.w);
            ull X23 = pk2(cc.x, cd.x),  Y23 = pk2(cc.y, cd.y);
            ull Z23 = pk2(cc.z, cd.z),  S23 = pk2(cc.w, cd.w);
            int tb = c0 + t - lane;                   // warp-uniform
#pragma unroll
            for (int u = 0; u < QW; u++) {
                ull d01 = mul2(qxp[u], X01);
                fma2(d01, qyp[u], Y01);
                fma2(d01, qzp[u], Z01);
                ull e01 = S01; fma2(e01, n2p, d01);   // e = csq - 2*dot
                ull d23 = mul2(qxp[u], X23);
                fma2(d23, qyp[u], Y23);
                fma2(d23, qzp[u], Z23);
                ull e23 = S23; fma2(e23, n2p, d23);
                float2 f01 = unpk2(e01);
                float2 f23 = unpk2(e23);
                float mn = fminf(fminf(f01.x, f01.y), fminf(f23.x, f23.y));
                if (__any_sync(full, mn < thr[u])) {
                    try_insert(f01.x, tb,      val[u], idx[u], thr[u]);
                    try_insert(f01.y, tb + 32, val[u], idx[u], thr[u]);
                    try_insert(f23.x, tb + 64, val[u], idx[u], thr[u]);
                    try_insert(f23.y, tb + 96, val[u], idx[u], thr[u]);
                }
            }
        }
    }

    if (lane < KNN) {
#pragma unroll
        for (int u = 0; u < QW; u++)
            out_idx[((size_t)b * NPTS + qbase + u) * KNN + lane] = idx[u];
    }
}

// ---------------- attention over K=8 neighbors (writes bf16 hi/lo agg) ----------
__global__ __launch_bounds__(256) void attn_kernel(const float* __restrict__ coords,
                                                   const float* __restrict__ logg)
{
    const int gq   = blockIdx.x * 8 + (threadIdx.x >> 5);
    const int b    = gq >> 13;
    const int q    = gq & (NPTS - 1);
    const int lane = threadIdx.x & 31;
    const float lg = *logg;
    const float inv_sqrt_c = 0.08838834764831845f;   // 1/sqrt(128)

    const float* qrow = g_q + (size_t)gq * CH;
    float qv[4];
#pragma unroll
    for (int p = 0; p < 4; p++) qv[p] = qrow[lane + 32 * p];

    const float* cb = coords + (size_t)b * NPTS * 3;
    const float qx = cb[q * 3 + 0], qy = cb[q * 3 + 1], qz = cb[q * 3 + 2];

    int nb[KNN];
#pragma unroll
    for (int t = 0; t < KNN; t++) nb[t] = g_idx[(size_t)gq * KNN + t];

    float sc[KNN];
#pragma unroll
    for (int t = 0; t < KNN; t++) {
        const float* kr = g_k + ((size_t)b * NPTS + nb[t]) * CH;
        float d = 0.f;
#pragma unroll
        for (int p = 0; p < 4; p++) d = fmaf(qv[p], kr[lane + 32 * p], d);
#pragma unroll
        for (int off = 16; off; off >>= 1) d += __shfl_xor_sync(0xffffffffu, d, off);
        float dx = qx - cb[nb[t] * 3 + 0];
        float dy = qy - cb[nb[t] * 3 + 1];
        float dz = qz - cb[nb[t] * 3 + 2];
        float d2 = fmaf(dz, dz, fmaf(dy, dy, dx * dx));
        float dist = (d2 > 0.f) ? sqrtf(d2) : 0.f;     // _safe_norm
        float gw = expf(lg * dist);
        sc[t] = d * inv_sqrt_c * gw;
    }
    float m = sc[0];
#pragma unroll
    for (int t = 1; t < KNN; t++) m = fmaxf(m, sc[t]);
    float ssum = 0.f;
#pragma unroll
    for (int t = 0; t < KNN; t++) { sc[t] = expf(sc[t] - m); ssum += sc[t]; }
    float inv = 1.f / ssum;

    float acc[4] = {0.f, 0.f, 0.f, 0.f};
#pragma unroll
    for (int t = 0; t < KNN; t++) {
        const float* vr = g_v + ((size_t)b * NPTS + nb[t]) * CH;
        float wt = sc[t] * inv;
#pragma unroll
        for (int p = 0; p < 4; p++) acc[p] = fmaf(wt, vr[lane + 32 * p], acc[p]);
    }
    // write agg directly in bf16 hi/lo X-pattern for the output GEMM
#pragma unroll
    for (int p = 0; p < 4; p++) {
        unsigned pk = pack_hilo(acc[p]);
        ((uint2*)g_agg2)[(size_t)gq * 128 + lane + 32 * p] = make_uint2(pk, pk);
    }
}

// ---------------- launch ----------------
extern "C" void kernel_launch(void* const* d_in, const int* in_sizes, int n_in,
                              void* d_out, int out_size)
{
    const float* feats  = (const float*)d_in[0];
    const float* coords = (const float*)d_in[1];
    const float* Wq     = (const float*)d_in[2];
    const float* Wk     = (const float*)d_in[3];
    const float* Wv     = (const float*)d_in[4];
    const float* Wo     = (const float*)d_in[5];
    const float* logg   = (const float*)d_in[6];
    float* out = (float*)d_out;

    int* idx_ptr = nullptr;
    cudaGetSymbolAddress((void**)&idx_ptr, g_idx);

    // split weights into bf16 hi/lo
    conv_w_kernel<<<4 * CH * CH / 256, 256>>>(Wq, Wk, Wv, Wo);

    // q,k,v projections on tensor cores (feats converted inline)
    qkv_mma_kernel<<<dim3(MTOT / 128, 3), 256>>>(feats);

    // KNN top-8 per query
    knn_kernel<<<dim3(NPTS / (WARPS * QW), BATCH), 256>>>(coords, idx_ptr);

    // neighbor attention -> g_agg2 (bf16 hi/lo)
    attn_kernel<<<MTOT / 8, 256>>>(coords, logg);

    // output projection on tensor cores
    out_mma_kernel<<<MTOT / 128, 256>>>(out);
}